// round 7
// baseline (speedup 1.0000x reference)
#include <cuda_runtime.h>
#include <cuda_bf16.h>

#define FULL 0xffffffffu
typedef unsigned long long u64;

// Packed f32x2 primitives (sm_103a FFMA2 path, PTX-only)
#define MK2(d, lo, hi)   asm("mov.b64 %0, {%1, %2};" : "=l"(d) : "f"(lo), "f"(hi))
#define UP2(lo, hi, s)   asm("mov.b64 {%0, %1}, %2;" : "=f"(lo), "=f"(hi) : "l"(s))
#define PMUL(d, a, b)    asm("mul.rn.f32x2 %0, %1, %2;" : "=l"(d) : "l"(a), "l"(b))
#define PFMA(d, a, b, c) asm("fma.rn.f32x2 %0, %1, %2, %3;" : "=l"(d) : "l"(a), "l"(b), "l"(c))
#define PADD(d, a, b)    asm("add.rn.f32x2 %0, %1, %2;" : "=l"(d) : "l"(a), "l"(b))

__device__ __forceinline__ u64 paxpby(u64 A, u64 X, u64 B, u64 Y) {
    u64 t, d; PMUL(t, B, Y); PFMA(d, A, X, t); return d;
}
__device__ __forceinline__ u64 dup2(float v) { u64 d; MK2(d, v, v); return d; }

// Layout: 4 batch elements per warp (8 lanes each; element = lane>>3).
// Amplitude index i: bits 0-2 = lane bits, bits 3-7 = register bits.
// Pack slot = amp bit3; pack index j (4 bits) = amp bits 4-7 (srp[16]/sip[16]).
// Qubit q lives on amplitude bit (7-q).
//
// Observable pushback: Z_q commutes with CRX(c,t) unless t==q.  Targets are
// qubit 3 only for CRX2, qubit 7 only for CRX6, so
//   f0 = Z3-signed norm after CRX0..2,   f1 = Z7-signed norm after CRX0..6,
// and CRX7..9 are dropped entirely (exact identity).

__global__ void __launch_bounds__(128, 6)
vqc_kernel(const float* __restrict__ x,         // (B, 4, 8)
           const float* __restrict__ crx_theta, // (10,)
           const float* __restrict__ w1,        // (10, 2)
           const float* __restrict__ b1,        // (10,)
           const float* __restrict__ w2,        // (1, 10)
           const float* __restrict__ b2,        // (1,)
           float* __restrict__ out,             // (B, 1)
           int n_batch) {
    const int warp = (int)((blockIdx.x * blockDim.x + threadIdx.x) >> 5);
    const int lane = threadIdx.x & 31;
    const int e0   = warp * 4;
    if (e0 >= n_batch) return;
    const int gb = lane & 24;      // element group base lane
    const int lo = lane & 7;

    // Angles: each of the 8 lanes of an element holds 4 of its 32 angles.
    int em = e0 + (lane >> 3);
    int eL = em < n_batch ? em : n_batch - 1;
    const float* xb = x + (size_t)eL * 32;
    float acv[4], asv[4];
    #pragma unroll
    for (int k = 0; k < 4; k++) {
        float a = xb[lo + k * 8];
        __sincosf(0.5f * a, &asv[k], &acv[k]);
    }

    // CRX thetas (batch-uniform): only gates 0..6 are needed; lanes 0-6 hold them.
    float thA = __ldg(&crx_theta[lo]);
    float csnA, ccoA;
    __sincosf(0.5f * thA, &csnA, &ccoA);

    u64 srp[16], sip[16];

    // ---------------- Cycle 0: closed form ----------------
    {
        float cq[8], sq[8];
        #pragma unroll
        for (int q = 0; q < 8; q++) {
            cq[q] = __shfl_sync(FULL, acv[0], gb | q);
            sq[q] = __shfl_sync(FULL, asv[0], gb | q);
        }
        const int x0 = lane & 1, x1 = (lane >> 1) & 1, x2 = (lane >> 2) & 1;
        float Lbase = ((x0 ^ x1) ? sq[7] : cq[7]) * ((x1 ^ x2) ? sq[6] : cq[6]);
        float f2_0 = x2 ? sq[5] : cq[5];
        float f2_1 = x2 ? cq[5] : sq[5];
        float f6_0 = x0 ? sq[1] : cq[1];
        float f6_1 = x0 ? cq[1] : sq[1];
        float f7_0 = x0 ? sq[0] : cq[0];
        float f7_1 = x0 ? cq[0] : sq[0];
        float A0 = Lbase * f2_0, A1 = Lbase * f2_1;
        float A00 = A0 * cq[4], A01 = A0 * sq[4];
        float A10 = A1 * sq[4], A11 = A1 * cq[4];
        #pragma unroll
        for (int j = 0; j < 16; j++) {
            const int b4 = j & 1, b5 = (j >> 1) & 1, b6 = (j >> 2) & 1, b7 = (j >> 3) & 1;
            float w = ((b4 ^ b5) ? sq[3] : cq[3])
                    * ((b5 ^ b6) ? sq[2] : cq[2])
                    * ((b6 ^ b7) ? f6_1 : f6_0)
                    * (b7 ? f7_1 : f7_0);
            float l_ = (b4 ? A01 : A00) * w;
            float h_ = (b4 ? A11 : A10) * w;
            MK2(srp[j], l_, h_);
        }
    }

    // ---------------- Cycles 1..3: fused RY+CNOT ----------------
    #pragma unroll
    for (int k = 1; k < 4; k++) {
        float c_, s_;
        #define BCAST(q) { c_ = __shfl_sync(FULL, acv[k], gb | (q)); \
                           s_ = __shfl_sync(FULL, asv[k], gb | (q)); }

        BCAST(0)
        if (k == 1) {
            u64 CC = dup2(c_), SS = dup2(s_), NS = dup2(-s_);
            #pragma unroll
            for (int j = 0; j < 8; j++) {
                u64 a = srp[j], b = srp[j + 8];
                srp[j]     = paxpby(CC, a, NS, b);
                srp[j + 8] = paxpby(SS, a, CC, b);
            }
        } else {
            bool g = lane & 1;
            u64 AL0 = dup2(g ? -s_ : c_), GA0 = dup2(g ? c_ : -s_);
            u64 AL1 = dup2(g ?  s_ : c_), GA1 = dup2(g ? c_ :  s_);
            #pragma unroll
            for (int j = 0; j < 8; j++) {
                u64 a = srp[j], b = srp[j + 8];
                srp[j]     = paxpby(AL0, a, GA0, b);
                srp[j + 8] = paxpby(AL1, b, GA1, a);
            }
        }
        #define RGATE(DIST, CB) {                                            \
            u64 CC = dup2(c_), SS = dup2(s_), NS = dup2(-s_);                \
            _Pragma("unroll")                                                \
            for (int j = 0; j < 16; j++) {                                   \
                if (!(j & (DIST))) {                                         \
                    const int j2 = j | (DIST);                               \
                    u64 a = srp[j], b = srp[j2];                             \
                    u64 n0 = paxpby(CC, a, NS, b);                           \
                    u64 n1 = paxpby(SS, a, CC, b);                           \
                    if (j & (CB)) { srp[j] = n1; srp[j2] = n0; }             \
                    else          { srp[j] = n0; srp[j2] = n1; }             \
                }                                                            \
            } }
        BCAST(1) RGATE(4, 8)
        BCAST(2) RGATE(2, 4)
        BCAST(3) RGATE(1, 2)
        #undef RGATE
        BCAST(4)
        {
            u64 CC = dup2(c_);
            u64 SV; MK2(SV, -s_, s_);
            u64 SW; MK2(SW, s_, -s_);
            #pragma unroll
            for (int j = 0; j < 16; j++) {
                float a0, a1; UP2(a0, a1, srp[j]);
                u64 rv; MK2(rv, a1, a0);
                if (j & 1) srp[j] = paxpby(CC, rv, SW, srp[j]);
                else       srp[j] = paxpby(CC, srp[j], SV, rv);
            }
        }
        BCAST(5)
        {
            float t = ((lane >> 2) & 1) ? s_ : -s_;
            u64 ALv; MK2(ALv, c_, -t);
            u64 GAv; MK2(GAv, t, c_);
            #pragma unroll
            for (int j = 0; j < 16; j++) {
                u64 p = __shfl_xor_sync(FULL, srp[j], 4);
                srp[j] = paxpby(ALv, srp[j], GAv, p);
            }
        }
        #define LGATE(B) {                                                   \
            float t = ((lane >> (B)) & 1) ? s_ : -s_;                        \
            bool  g = (lane >> ((B) + 1)) & 1;                               \
            u64 AL = dup2(g ? -t : c_);                                      \
            u64 GA = dup2(g ?  c_ : t);                                      \
            _Pragma("unroll")                                                \
            for (int j = 0; j < 16; j++) {                                   \
                u64 p = __shfl_xor_sync(FULL, srp[j], 1 << (B));             \
                srp[j] = paxpby(AL, srp[j], GA, p);                          \
            } }
        BCAST(6) LGATE(1)
        BCAST(7) LGATE(0)
        #undef LGATE
        #undef BCAST
    }
    // Cycle 3's trailing CNOT(0,7): conditional pack swap (j <-> j+8)
    {
        bool g = lane & 1;
        #pragma unroll
        for (int j = 0; j < 8; j++) {
            u64 a = srp[j], b = srp[j + 8];
            srp[j]     = g ? b : a;
            srp[j + 8] = g ? a : b;
        }
    }

    // ---------------- CRX gates 0..6 ----------------
    #define CBC(i) float co = __shfl_sync(FULL, ccoA, gb | (i)); \
                   float sn = __shfl_sync(FULL, csnA, gb | (i));

    // CRX0: ctrl bit7 (j&8), tgt bit6 -> pairs (8,12)..(11,15); si==0 (RE)
    { CBC(0)
      u64 CO = dup2(co), NSN = dup2(-sn);
      #pragma unroll
      for (int j = 8; j < 12; j++) {
          const int jb = j + 4;
          u64 a = srp[j], b = srp[jb];
          PMUL(srp[j],  CO,  a);  PMUL(sip[j],  NSN, b);
          PMUL(srp[jb], CO,  b);  PMUL(sip[jb], NSN, a);
      } }
    // CRX1: ctrl bit6 (j&4), tgt bit5 -> (4,6),(5,7) RE + (12,14),(13,15) FULL
    { CBC(1)
      u64 CO = dup2(co), SN = dup2(sn), NSN = dup2(-sn);
      #pragma unroll
      for (int j = 4; j < 6; j++) {
          const int jb = j + 2;
          u64 a = srp[j], b = srp[jb];
          PMUL(srp[j],  CO, a);  PMUL(sip[j],  NSN, b);
          PMUL(srp[jb], CO, b);  PMUL(sip[jb], NSN, a);
      }
      #pragma unroll
      for (int j = 12; j < 14; j++) {
          const int jb = j + 2;
          u64 ar = srp[j], ai = sip[j], br = srp[jb], bi = sip[jb];
          srp[j]  = paxpby(CO, ar, SN,  bi);  sip[j]  = paxpby(CO, ai, NSN, br);
          srp[jb] = paxpby(CO, br, SN,  ai);  sip[jb] = paxpby(CO, bi, NSN, ar);
      } }
    // CRX2: ctrl bit5 (j&2), tgt bit4 -> (2,3) RE + (6,7),(10,11),(14,15) FULL
    { CBC(2)
      u64 CO = dup2(co), SN = dup2(sn), NSN = dup2(-sn);
      { u64 a = srp[2], b = srp[3];
        PMUL(srp[2], CO, a);  PMUL(sip[2], NSN, b);
        PMUL(srp[3], CO, b);  PMUL(sip[3], NSN, a); }
      #pragma unroll
      for (int j = 6; j < 16; j += 4) {
          const int jb = j + 1;
          u64 ar = srp[j], ai = sip[j], br = srp[jb], bi = sip[jb];
          srp[j]  = paxpby(CO, ar, SN,  bi);  sip[j]  = paxpby(CO, ai, NSN, br);
          srp[jb] = paxpby(CO, br, SN,  ai);  sip[jb] = paxpby(CO, bi, NSN, ar);
      } }

    // ---- f0 snapshot: Z3-signed norm (sign = pack parity j&1).  si is
    //      nonzero only on packs 2..15 at this point. ----
    float f0p;
    {
        u64 accP, accM;
        { float z0 = 0.0f; MK2(accP, z0, z0); MK2(accM, z0, z0); }
        #pragma unroll
        for (int j = 0; j < 16; j += 2) {
            PFMA(accP, srp[j],     srp[j],     accP);
            PFMA(accM, srp[j + 1], srp[j + 1], accM);
        }
        #pragma unroll
        for (int j = 2; j < 16; j += 2) PFMA(accP, sip[j], sip[j], accP);
        #pragma unroll
        for (int j = 3; j < 16; j += 2) PFMA(accM, sip[j], sip[j], accM);
        float p0, p1, m0, m1;
        UP2(p0, p1, accP);  UP2(m0, m1, accM);
        f0p = (p0 + p1) - (m0 + m1);
    }

    // CRX3: ctrl bit4 (j&1, odd packs), tgt bit3 (within pack); pack1 RE, rest FULL
    { CBC(3)
      u64 CO = dup2(co), SN = dup2(sn), NSN = dup2(-sn);
      { float a0, a1; UP2(a0, a1, srp[1]);
        u64 rv; MK2(rv, a1, a0);
        PMUL(srp[1], CO, srp[1]);
        PMUL(sip[1], NSN, rv); }
      #pragma unroll
      for (int j = 3; j < 16; j += 2) {
          float r0, r1, i0, i1;
          UP2(r0, r1, srp[j]);  UP2(i0, i1, sip[j]);
          u64 rvr; MK2(rvr, r1, r0);
          u64 rvi; MK2(rvi, i1, i0);
          srp[j] = paxpby(CO, srp[j], SN,  rvi);
          sip[j] = paxpby(CO, sip[j], NSN, rvr);
      } }
    // CRX4: ctrl bit3 (slot), tgt bit2 (lane mask 4); per-slot coeffs (1,co)/(0,sn)
    { CBC(4)
      u64 COe; MK2(COe, 1.0f, co);
      u64 SNe; MK2(SNe, 0.0f, sn);
      u64 NSNe; MK2(NSNe, 0.0f, -sn);
      { // pack 0: si still zero -> skip si shuffle
        u64 pr = __shfl_xor_sync(FULL, srp[0], 4);
        u64 t = srp[0];
        PMUL(srp[0], COe, t);
        PMUL(sip[0], NSNe, pr); }
      #pragma unroll
      for (int j = 1; j < 16; j++) {
          u64 pr = __shfl_xor_sync(FULL, srp[j], 4);
          u64 pi = __shfl_xor_sync(FULL, sip[j], 4);
          srp[j] = paxpby(COe, srp[j], SNe,  pi);
          sip[j] = paxpby(COe, sip[j], NSNe, pr);
      } }
    // CRX5/6: lane ctrl, lane target (fold ctrl into coefficients)
    #define CRXL(CB, MASK) {                                                 \
        bool  g    = (lane >> (CB)) & 1;                                     \
        float co_e = g ? co : 1.0f;                                          \
        float sn_e = g ? sn : 0.0f;                                          \
        u64 COe = dup2(co_e), SNe = dup2(sn_e), NSNe = dup2(-sn_e);          \
        _Pragma("unroll")                                                    \
        for (int j = 0; j < 16; j++) {                                       \
            u64 pr = __shfl_xor_sync(FULL, srp[j], MASK);                    \
            u64 pi = __shfl_xor_sync(FULL, sip[j], MASK);                    \
            srp[j] = paxpby(COe, srp[j], SNe,  pi);                          \
            sip[j] = paxpby(COe, sip[j], NSNe, pr);                          \
        } }
    { CBC(5) CRXL(2, 2) }
    { CBC(6) CRXL(1, 1) }
    #undef CRXL
    #undef CBC
    // (CRX7..9 cancel out of both observables — dropped.)

    // ---- f1 snapshot: Z7-signed norm (sign = lane bit0) ----
    float f1p;
    {
        u64 acc;
        { float z0 = 0.0f; MK2(acc, z0, z0); }
        #pragma unroll
        for (int j = 0; j < 16; j++) {
            PFMA(acc, srp[j], srp[j], acc);
            PFMA(acc, sip[j], sip[j], acc);
        }
        float t0, t1; UP2(t0, t1, acc);
        float T = t0 + t1;
        f1p = (lane & 1) ? -T : T;
    }

    // ---------------- Reduction + MLP ----------------
    float f0, f1;
    u64 fv; MK2(fv, f0p, f1p);
    #pragma unroll
    for (int m = 4; m >= 1; m >>= 1) {
        u64 p = __shfl_xor_sync(FULL, fv, m);
        PADD(fv, fv, p);
    }
    UP2(f0, f1, fv);

    // Hidden units: lane lo handles unit lo; lanes 0,1 also units 8,9.
    float z1 = fmaf(f0, __ldg(&w1[lo * 2 + 0]),
               fmaf(f1, __ldg(&w1[lo * 2 + 1]), __ldg(&b1[lo])));
    float contrib = tanhf(z1) * __ldg(&w2[lo]);
    if (lo < 2) {
        const int u = 8 + lo;
        float z2 = fmaf(f0, __ldg(&w1[u * 2 + 0]),
                   fmaf(f1, __ldg(&w1[u * 2 + 1]), __ldg(&b1[u])));
        contrib += tanhf(z2) * __ldg(&w2[u]);
    }
    #pragma unroll
    for (int m = 4; m >= 1; m >>= 1)
        contrib += __shfl_xor_sync(FULL, contrib, m);

    if (lo == 0 && em < n_batch) {
        float z = contrib + __ldg(&b2[0]);
        out[em] = 1.0f / (1.0f + __expf(-z));
    }
}

extern "C" void kernel_launch(void* const* d_in, const int* in_sizes, int n_in,
                              void* d_out, int out_size) {
    const float* x         = (const float*)d_in[0];
    const float* crx_theta = (const float*)d_in[1];
    const float* w1        = (const float*)d_in[2];
    const float* b1        = (const float*)d_in[3];
    const float* w2        = (const float*)d_in[4];
    const float* b2        = (const float*)d_in[5];
    float* out = (float*)d_out;

    const int n_batch = in_sizes[0] / 32;            // (B,4,8) -> B
    const int nwarps  = (n_batch + 3) / 4;           // 4 elements per warp
    const int threads = 128;                         // 4 warps per block
    const int blocks  = (nwarps + 3) / 4;
    vqc_kernel<<<blocks, threads>>>(x, crx_theta, w1, b1, w2, b2, out, n_batch);
}

// round 8
// speedup vs baseline: 1.1212x; 1.1212x over previous
#include <cuda_runtime.h>
#include <cuda_bf16.h>

#define FULL 0xffffffffu
typedef unsigned long long u64;

// Packed f32x2 primitives (sm_103a FFMA2 path, PTX-only)
#define MK2(d, lo, hi)   asm("mov.b64 %0, {%1, %2};" : "=l"(d) : "f"(lo), "f"(hi))
#define UP2(lo, hi, s)   asm("mov.b64 {%0, %1}, %2;" : "=f"(lo), "=f"(hi) : "l"(s))
#define PMUL(d, a, b)    asm("mul.rn.f32x2 %0, %1, %2;" : "=l"(d) : "l"(a), "l"(b))
#define PFMA(d, a, b, c) asm("fma.rn.f32x2 %0, %1, %2, %3;" : "=l"(d) : "l"(a), "l"(b), "l"(c))
#define PADD(d, a, b)    asm("add.rn.f32x2 %0, %1, %2;" : "=l"(d) : "l"(a), "l"(b))

__device__ __forceinline__ u64 paxpby(u64 A, u64 X, u64 B, u64 Y) {
    u64 t, d; PMUL(t, B, Y); PFMA(d, A, X, t); return d;
}
__device__ __forceinline__ u64 dup2(float v) { u64 d; MK2(d, v, v); return d; }

// Layout: 4 batch elements per warp (8 lanes each; element = lane>>3).
// Amplitude index i: bits 0-2 = lane bits, bits 3-7 = register bits.
// Pack slot = amp bit3; pack index j (4 bits) = amp bits 4-7 (srp[16]/sip[16]).
// Qubit q lives on amplitude bit (7-q).
//
// Observable pushback: Z_q commutes with CRX(c,t) unless t==q.  Targets are
// qubit 3 only for CRX2, qubit 7 only for CRX6, so
//   f0 = Z3-signed norm after CRX0..2,   f1 = Z7-signed norm after CRX0..6,
// and CRX7..9 are dropped entirely (exact identity).

__global__ void __launch_bounds__(128)
vqc_kernel(const float* __restrict__ x,         // (B, 4, 8)
           const float* __restrict__ crx_theta, // (10,)
           const float* __restrict__ w1,        // (10, 2)
           const float* __restrict__ b1,        // (10,)
           const float* __restrict__ w2,        // (1, 10)
           const float* __restrict__ b2,        // (1,)
           float* __restrict__ out,             // (B, 1)
           int n_batch) {
    const int warp = (int)((blockIdx.x * blockDim.x + threadIdx.x) >> 5);
    const int lane = threadIdx.x & 31;
    const int e0   = warp * 4;
    if (e0 >= n_batch) return;
    const int gb = lane & 24;      // element group base lane
    const int lo = lane & 7;

    // Raw angles: each of the 8 lanes of an element holds its qubit's angle for
    // all 4 cycles (sincos computed per cycle to keep the live set small).
    int em = e0 + (lane >> 3);
    int eL = em < n_batch ? em : n_batch - 1;
    const float* xb = x + (size_t)eL * 32;
    float ang[4];
    #pragma unroll
    for (int k = 0; k < 4; k++) ang[k] = xb[lo + k * 8];

    u64 srp[16], sip[16];

    // ---------------- Cycle 0: closed form ----------------
    {
        float mys, myc;
        __sincosf(0.5f * ang[0], &mys, &myc);
        float cq[8], sq[8];
        #pragma unroll
        for (int q = 0; q < 8; q++) {
            cq[q] = __shfl_sync(FULL, myc, gb | q);
            sq[q] = __shfl_sync(FULL, mys, gb | q);
        }
        const int x0 = lane & 1, x1 = (lane >> 1) & 1, x2 = (lane >> 2) & 1;
        float Lbase = ((x0 ^ x1) ? sq[7] : cq[7]) * ((x1 ^ x2) ? sq[6] : cq[6]);
        float f2_0 = x2 ? sq[5] : cq[5];
        float f2_1 = x2 ? cq[5] : sq[5];
        float f6_0 = x0 ? sq[1] : cq[1];
        float f6_1 = x0 ? cq[1] : sq[1];
        float f7_0 = x0 ? sq[0] : cq[0];
        float f7_1 = x0 ? cq[0] : sq[0];
        float A0 = Lbase * f2_0, A1 = Lbase * f2_1;
        float A00 = A0 * cq[4], A01 = A0 * sq[4];
        float A10 = A1 * sq[4], A11 = A1 * cq[4];
        #pragma unroll
        for (int j = 0; j < 16; j++) {
            const int b4 = j & 1, b5 = (j >> 1) & 1, b6 = (j >> 2) & 1, b7 = (j >> 3) & 1;
            float w = ((b4 ^ b5) ? sq[3] : cq[3])
                    * ((b5 ^ b6) ? sq[2] : cq[2])
                    * ((b6 ^ b7) ? f6_1 : f6_0)
                    * (b7 ? f7_1 : f7_0);
            float l_ = (b4 ? A01 : A00) * w;
            float h_ = (b4 ? A11 : A10) * w;
            MK2(srp[j], l_, h_);
        }
    }

    // ---------------- Cycles 1..3: fused RY+CNOT ----------------
    #pragma unroll
    for (int k = 1; k < 4; k++) {
        float mys, myc;
        __sincosf(0.5f * ang[k], &mys, &myc);
        float c_, s_;
        #define BCAST(q) { c_ = __shfl_sync(FULL, myc, gb | (q)); \
                           s_ = __shfl_sync(FULL, mys, gb | (q)); }

        BCAST(0)
        if (k == 1) {
            u64 CC = dup2(c_), SS = dup2(s_), NS = dup2(-s_);
            #pragma unroll
            for (int j = 0; j < 8; j++) {
                u64 a = srp[j], b = srp[j + 8];
                srp[j]     = paxpby(CC, a, NS, b);
                srp[j + 8] = paxpby(SS, a, CC, b);
            }
        } else {
            bool g = lane & 1;
            u64 AL0 = dup2(g ? -s_ : c_), GA0 = dup2(g ? c_ : -s_);
            u64 AL1 = dup2(g ?  s_ : c_), GA1 = dup2(g ? c_ :  s_);
            #pragma unroll
            for (int j = 0; j < 8; j++) {
                u64 a = srp[j], b = srp[j + 8];
                srp[j]     = paxpby(AL0, a, GA0, b);
                srp[j + 8] = paxpby(AL1, b, GA1, a);
            }
        }
        #define RGATE(DIST, CB) {                                            \
            u64 CC = dup2(c_), SS = dup2(s_), NS = dup2(-s_);                \
            _Pragma("unroll")                                                \
            for (int j = 0; j < 16; j++) {                                   \
                if (!(j & (DIST))) {                                         \
                    const int j2 = j | (DIST);                               \
                    u64 a = srp[j], b = srp[j2];                             \
                    u64 n0 = paxpby(CC, a, NS, b);                           \
                    u64 n1 = paxpby(SS, a, CC, b);                           \
                    if (j & (CB)) { srp[j] = n1; srp[j2] = n0; }             \
                    else          { srp[j] = n0; srp[j2] = n1; }             \
                }                                                            \
            } }
        BCAST(1) RGATE(4, 8)
        BCAST(2) RGATE(2, 4)
        BCAST(3) RGATE(1, 2)
        #undef RGATE
        BCAST(4)
        {
            u64 CC = dup2(c_);
            u64 SV; MK2(SV, -s_, s_);
            u64 SW; MK2(SW, s_, -s_);
            #pragma unroll
            for (int j = 0; j < 16; j++) {
                float a0, a1; UP2(a0, a1, srp[j]);
                u64 rv; MK2(rv, a1, a0);
                if (j & 1) srp[j] = paxpby(CC, rv, SW, srp[j]);
                else       srp[j] = paxpby(CC, srp[j], SV, rv);
            }
        }
        BCAST(5)
        {
            float t = ((lane >> 2) & 1) ? s_ : -s_;
            u64 ALv; MK2(ALv, c_, -t);
            u64 GAv; MK2(GAv, t, c_);
            #pragma unroll
            for (int j = 0; j < 16; j++) {
                u64 p = __shfl_xor_sync(FULL, srp[j], 4);
                srp[j] = paxpby(ALv, srp[j], GAv, p);
            }
        }
        #define LGATE(B) {                                                   \
            float t = ((lane >> (B)) & 1) ? s_ : -s_;                        \
            bool  g = (lane >> ((B) + 1)) & 1;                               \
            u64 AL = dup2(g ? -t : c_);                                      \
            u64 GA = dup2(g ?  c_ : t);                                      \
            _Pragma("unroll")                                                \
            for (int j = 0; j < 16; j++) {                                   \
                u64 p = __shfl_xor_sync(FULL, srp[j], 1 << (B));             \
                srp[j] = paxpby(AL, srp[j], GA, p);                          \
            } }
        BCAST(6) LGATE(1)
        BCAST(7) LGATE(0)
        #undef LGATE
        #undef BCAST
    }
    // Cycle 3's trailing CNOT(0,7): conditional pack swap (j <-> j+8)
    {
        bool g = lane & 1;
        #pragma unroll
        for (int j = 0; j < 8; j++) {
            u64 a = srp[j], b = srp[j + 8];
            srp[j]     = g ? b : a;
            srp[j + 8] = g ? a : b;
        }
    }

    // ---------------- CRX gates 0..6 ----------------
    // CRX thetas (batch-uniform, L2-resident): loaded only now to keep the
    // register live-set small through the cycle loop.
    float thA = __ldg(&crx_theta[lo]);
    float csnA, ccoA;
    __sincosf(0.5f * thA, &csnA, &ccoA);

    #define CBC(i) float co = __shfl_sync(FULL, ccoA, gb | (i)); \
                   float sn = __shfl_sync(FULL, csnA, gb | (i));

    // CRX0: ctrl bit7 (j&8), tgt bit6 -> pairs (8,12)..(11,15); si==0 (RE)
    { CBC(0)
      u64 CO = dup2(co), NSN = dup2(-sn);
      #pragma unroll
      for (int j = 8; j < 12; j++) {
          const int jb = j + 4;
          u64 a = srp[j], b = srp[jb];
          PMUL(srp[j],  CO,  a);  PMUL(sip[j],  NSN, b);
          PMUL(srp[jb], CO,  b);  PMUL(sip[jb], NSN, a);
      } }
    // CRX1: ctrl bit6 (j&4), tgt bit5 -> (4,6),(5,7) RE + (12,14),(13,15) FULL
    { CBC(1)
      u64 CO = dup2(co), SN = dup2(sn), NSN = dup2(-sn);
      #pragma unroll
      for (int j = 4; j < 6; j++) {
          const int jb = j + 2;
          u64 a = srp[j], b = srp[jb];
          PMUL(srp[j],  CO, a);  PMUL(sip[j],  NSN, b);
          PMUL(srp[jb], CO, b);  PMUL(sip[jb], NSN, a);
      }
      #pragma unroll
      for (int j = 12; j < 14; j++) {
          const int jb = j + 2;
          u64 ar = srp[j], ai = sip[j], br = srp[jb], bi = sip[jb];
          srp[j]  = paxpby(CO, ar, SN,  bi);  sip[j]  = paxpby(CO, ai, NSN, br);
          srp[jb] = paxpby(CO, br, SN,  ai);  sip[jb] = paxpby(CO, bi, NSN, ar);
      } }
    // CRX2: ctrl bit5 (j&2), tgt bit4 -> (2,3) RE + (6,7),(10,11),(14,15) FULL
    { CBC(2)
      u64 CO = dup2(co), SN = dup2(sn), NSN = dup2(-sn);
      { u64 a = srp[2], b = srp[3];
        PMUL(srp[2], CO, a);  PMUL(sip[2], NSN, b);
        PMUL(srp[3], CO, b);  PMUL(sip[3], NSN, a); }
      #pragma unroll
      for (int j = 6; j < 16; j += 4) {
          const int jb = j + 1;
          u64 ar = srp[j], ai = sip[j], br = srp[jb], bi = sip[jb];
          srp[j]  = paxpby(CO, ar, SN,  bi);  sip[j]  = paxpby(CO, ai, NSN, br);
          srp[jb] = paxpby(CO, br, SN,  ai);  sip[jb] = paxpby(CO, bi, NSN, ar);
      } }

    // ---- f0 snapshot: Z3-signed norm (sign = pack parity j&1).  si is
    //      nonzero only on packs 2..15 at this point. ----
    float f0p;
    {
        u64 accP, accM;
        { float z0 = 0.0f; MK2(accP, z0, z0); MK2(accM, z0, z0); }
        #pragma unroll
        for (int j = 0; j < 16; j += 2) {
            PFMA(accP, srp[j],     srp[j],     accP);
            PFMA(accM, srp[j + 1], srp[j + 1], accM);
        }
        #pragma unroll
        for (int j = 2; j < 16; j += 2) PFMA(accP, sip[j], sip[j], accP);
        #pragma unroll
        for (int j = 3; j < 16; j += 2) PFMA(accM, sip[j], sip[j], accM);
        float p0, p1, m0, m1;
        UP2(p0, p1, accP);  UP2(m0, m1, accM);
        f0p = (p0 + p1) - (m0 + m1);
    }

    // CRX3: ctrl bit4 (j&1, odd packs), tgt bit3 (within pack); pack1 RE, rest FULL
    { CBC(3)
      u64 CO = dup2(co), SN = dup2(sn), NSN = dup2(-sn);
      { float a0, a1; UP2(a0, a1, srp[1]);
        u64 rv; MK2(rv, a1, a0);
        PMUL(srp[1], CO, srp[1]);
        PMUL(sip[1], NSN, rv); }
      #pragma unroll
      for (int j = 3; j < 16; j += 2) {
          float r0, r1, i0, i1;
          UP2(r0, r1, srp[j]);  UP2(i0, i1, sip[j]);
          u64 rvr; MK2(rvr, r1, r0);
          u64 rvi; MK2(rvi, i1, i0);
          srp[j] = paxpby(CO, srp[j], SN,  rvi);
          sip[j] = paxpby(CO, sip[j], NSN, rvr);
      } }
    // CRX4: ctrl bit3 (slot), tgt bit2 (lane mask 4); per-slot coeffs (1,co)/(0,sn)
    { CBC(4)
      u64 COe; MK2(COe, 1.0f, co);
      u64 SNe; MK2(SNe, 0.0f, sn);
      u64 NSNe; MK2(NSNe, 0.0f, -sn);
      { // pack 0: si still zero -> skip si shuffle
        u64 pr = __shfl_xor_sync(FULL, srp[0], 4);
        u64 t = srp[0];
        PMUL(srp[0], COe, t);
        PMUL(sip[0], NSNe, pr); }
      #pragma unroll
      for (int j = 1; j < 16; j++) {
          u64 pr = __shfl_xor_sync(FULL, srp[j], 4);
          u64 pi = __shfl_xor_sync(FULL, sip[j], 4);
          srp[j] = paxpby(COe, srp[j], SNe,  pi);
          sip[j] = paxpby(COe, sip[j], NSNe, pr);
      } }
    // CRX5/6: lane ctrl, lane target (fold ctrl into coefficients)
    #define CRXL(CB, MASK) {                                                 \
        bool  g    = (lane >> (CB)) & 1;                                     \
        float co_e = g ? co : 1.0f;                                          \
        float sn_e = g ? sn : 0.0f;                                          \
        u64 COe = dup2(co_e), SNe = dup2(sn_e), NSNe = dup2(-sn_e);          \
        _Pragma("unroll")                                                    \
        for (int j = 0; j < 16; j++) {                                       \
            u64 pr = __shfl_xor_sync(FULL, srp[j], MASK);                    \
            u64 pi = __shfl_xor_sync(FULL, sip[j], MASK);                    \
            srp[j] = paxpby(COe, srp[j], SNe,  pi);                          \
            sip[j] = paxpby(COe, sip[j], NSNe, pr);                          \
        } }
    { CBC(5) CRXL(2, 2) }
    { CBC(6) CRXL(1, 1) }
    #undef CRXL
    #undef CBC
    // (CRX7..9 cancel out of both observables — dropped.)

    // ---- f1 snapshot: Z7-signed norm (sign = lane bit0) ----
    float f1p;
    {
        u64 acc;
        { float z0 = 0.0f; MK2(acc, z0, z0); }
        #pragma unroll
        for (int j = 0; j < 16; j++) {
            PFMA(acc, srp[j], srp[j], acc);
            PFMA(acc, sip[j], sip[j], acc);
        }
        float t0, t1; UP2(t0, t1, acc);
        float T = t0 + t1;
        f1p = (lane & 1) ? -T : T;
    }

    // ---------------- Reduction + MLP ----------------
    float f0, f1;
    u64 fv; MK2(fv, f0p, f1p);
    #pragma unroll
    for (int m = 4; m >= 1; m >>= 1) {
        u64 p = __shfl_xor_sync(FULL, fv, m);
        PADD(fv, fv, p);
    }
    UP2(f0, f1, fv);

    // Hidden units: lane lo handles unit lo; lanes 0,1 also units 8,9.
    float z1 = fmaf(f0, __ldg(&w1[lo * 2 + 0]),
               fmaf(f1, __ldg(&w1[lo * 2 + 1]), __ldg(&b1[lo])));
    float contrib = tanhf(z1) * __ldg(&w2[lo]);
    if (lo < 2) {
        const int u = 8 + lo;
        float z2 = fmaf(f0, __ldg(&w1[u * 2 + 0]),
                   fmaf(f1, __ldg(&w1[u * 2 + 1]), __ldg(&b1[u])));
        contrib += tanhf(z2) * __ldg(&w2[u]);
    }
    #pragma unroll
    for (int m = 4; m >= 1; m >>= 1)
        contrib += __shfl_xor_sync(FULL, contrib, m);

    if (lo == 0 && em < n_batch) {
        float z = contrib + __ldg(&b2[0]);
        out[em] = 1.0f / (1.0f + __expf(-z));
    }
}

extern "C" void kernel_launch(void* const* d_in, const int* in_sizes, int n_in,
                              void* d_out, int out_size) {
    const float* x         = (const float*)d_in[0];
    const float* crx_theta = (const float*)d_in[1];
    const float* w1        = (const float*)d_in[2];
    const float* b1        = (const float*)d_in[3];
    const float* w2        = (const float*)d_in[4];
    const float* b2        = (const float*)d_in[5];
    float* out = (float*)d_out;

    const int n_batch = in_sizes[0] / 32;            // (B,4,8) -> B
    const int nwarps  = (n_batch + 3) / 4;           // 4 elements per warp
    const int threads = 128;                         // 4 warps per block
    const int blocks  = (nwarps + 3) / 4;
    vqc_kernel<<<blocks, threads>>>(x, crx_theta, w1, b1, w2, b2, out, n_batch);
}